// round 13
// baseline (speedup 1.0000x reference)
#include <cuda_runtime.h>
#include <cuda_bf16.h>
#include <cstdint>

#define NUM_CHR 24
#define N_EMB   512
#define DIM     512
#define BATCH   1024

#define MT 64
#define NT 128
#define KB 32
#define KSPLIT 4
#define KCH (N_EMB / KSPLIT)   // 128
#define MTILES 2
#define NTILES (DIM / NT)      // 4

#define AS_STRIDE 72            // words; bank(k,m) = (8k + m) % 32
#define BS_STRIDE 136           // words; bank(k,n) = (8k + n) % 32

// ---------------- scratch (device-code references only) ----------------
__device__ float g_W[BATCH * N_EMB];
__device__ int   g_order[BATCH];
__device__ int   g_start[NUM_CHR + 1];
__device__ float g_part[KSPLIT * BATCH * DIM];

// ---------------- tf32 helpers ----------------
__device__ __forceinline__ uint32_t f2tf(float f) {
    uint32_t r; asm("cvt.rna.tf32.f32 %0, %1;" : "=r"(r) : "f"(f)); return r;
}
#define HMMA(d, a0, a1, a2, a3, b0, b1)                                      \
    asm("mma.sync.aligned.m16n8k8.row.col.f32.tf32.tf32.f32 "                \
        "{%0,%1,%2,%3},{%4,%5,%6,%7},{%8,%9},{%0,%1,%2,%3};"                 \
        : "+f"((d)[0]), "+f"((d)[1]), "+f"((d)[2]), "+f"((d)[3])             \
        : "r"(a0), "r"(a1), "r"(a2), "r"(a3), "r"(b0), "r"(b1))

// ---------------- kernel 1: weights (2 warps/sample) + grouping ----------
__global__ void __launch_bounds__(256) weights_group_kernel(
    const int* __restrict__ chrom,
    const float* __restrict__ pos,
    const float* __restrict__ centers,
    const float* __restrict__ logv)
{
    if (blockIdx.x == BATCH / 4) {
        // ---- grouping block: match_any + scans, zero atomics ----
        __shared__ int cnt[4][8][NUM_CHR];
        __shared__ int pre[4][8][NUM_CHR];
        __shared__ int base[NUM_CHR];
        __shared__ int tot[NUM_CHR];

        int t = threadIdx.x;
        int lane = t & 31, w = t >> 5;

        for (int i = t; i < 4 * 8 * NUM_CHR; i += 256) ((int*)cnt)[i] = 0;
        __syncthreads();

        int cs[4], lr[4];
#pragma unroll
        for (int r = 0; r < 4; r++) {
            int s = r * 256 + t;
            int c = chrom[s];
            unsigned mask = __match_any_sync(0xffffffffu, c);
            int leader = __ffs(mask) - 1;
            lr[r] = __popc(mask & ((1u << lane) - 1u));
            cs[r] = c;
            if (lane == leader) cnt[r][w][c] = __popc(mask);
        }
        __syncthreads();

        for (int c = w; c < NUM_CHR; c += 8) {
            int v = cnt[lane >> 3][lane & 7][c];
            int scan = v;
#pragma unroll
            for (int off = 1; off < 32; off <<= 1) {
                int n = __shfl_up_sync(0xffffffffu, scan, off);
                if (lane >= off) scan += n;
            }
            pre[lane >> 3][lane & 7][c] = scan - v;
            if (lane == 31) tot[c] = scan;
        }
        __syncthreads();

        if (w == 0) {
            int v = (lane < NUM_CHR) ? tot[lane] : 0;
            int scan = v;
#pragma unroll
            for (int off = 1; off < 32; off <<= 1) {
                int n = __shfl_up_sync(0xffffffffu, scan, off);
                if (lane >= off) scan += n;
            }
            if (lane < NUM_CHR) { base[lane] = scan - v; g_start[lane] = scan - v; }
            if (lane == NUM_CHR - 1) g_start[NUM_CHR] = scan;
        }
        __syncthreads();

#pragma unroll
        for (int r = 0; r < 4; r++) {
            int c = cs[r];
            g_order[base[c] + pre[r][w][c] + lr[r]] = r * 256 + t;
        }
        return;
    }

    // ---- weights: 2 warps per sample, 8 centers per lane ----
    __shared__ float ssum[8];
    int lane = threadIdx.x & 31, w = threadIdx.x >> 5;
    int b = blockIdx.x * 4 + (w >> 1);
    int half = w & 1;
    int c = chrom[b];
    float p = pos[b];

    const float* crow = centers + (size_t)c * N_EMB;
    const float* vrow = logv + (size_t)c * N_EMB;
    int n0 = half * 256 + lane * 8;

    float wv[8];
    float s = 0.f;
#pragma unroll
    for (int i = 0; i < 2; i++) {
        float4 cc = *(const float4*)(crow + n0 + i * 4);
        float4 lv = *(const float4*)(vrow + n0 + i * 4);
        float d, iv;
        d = p - cc.x; iv = __expf(-lv.x); wv[i*4+0] = __expf(-0.5f * d * d * iv);
        d = p - cc.y; iv = __expf(-lv.y); wv[i*4+1] = __expf(-0.5f * d * d * iv);
        d = p - cc.z; iv = __expf(-lv.z); wv[i*4+2] = __expf(-0.5f * d * d * iv);
        d = p - cc.w; iv = __expf(-lv.w); wv[i*4+3] = __expf(-0.5f * d * d * iv);
        s += wv[i*4+0] + wv[i*4+1] + wv[i*4+2] + wv[i*4+3];
    }
#pragma unroll
    for (int off = 16; off > 0; off >>= 1)
        s += __shfl_xor_sync(0xffffffffu, s, off);
    if (lane == 0) ssum[w] = s;
    __syncthreads();
    float inv = 1.f / (ssum[w] + ssum[w ^ 1]);

    float* wrow = g_W + (size_t)b * N_EMB + n0;
    *(float4*)(wrow + 0) = make_float4(wv[0] * inv, wv[1] * inv, wv[2] * inv, wv[3] * inv);
    *(float4*)(wrow + 4) = make_float4(wv[4] * inv, wv[5] * inv, wv[6] * inv, wv[7] * inv);
}

// ---------------- kernel 2: grouped GEMM, tf32 mma.sync, split-K ----------
// Block M64 x N128 x K128, 256 threads = 8 warps in 2m x 4n grid.
// Each warp: m32 x n32 slab -> 16 LDS.32 + 8 HMMA per k8-step.
__global__ void __launch_bounds__(256, 3) gemm_kernel(const float* __restrict__ E)
{
    int c  = blockIdx.z;
    int nt = blockIdx.x;
    int ks = blockIdx.y >> 1;
    int mt = blockIdx.y & 1;

    int s0  = g_start[c];
    int cnt = g_start[c + 1] - s0;
    int m0  = mt * MT;
    if (m0 >= cnt) return;

    __shared__ __align__(16) float As[KB][AS_STRIDE];
    __shared__ __align__(16) float Bs[KB][BS_STRIDE];
    __shared__ int sord[MT];

    int tid = threadIdx.x;
    int d0  = nt * NT;
    int kbase = ks * KCH;

    if (tid < MT) {
        int gmi = m0 + tid;
        sord[tid] = (gmi < cnt) ? g_order[s0 + gmi] : -1;
    }
    __syncthreads();

    int am  = tid & 63;
    int ak8 = (tid >> 6) * 8;
    int samp = sord[am];
    const float* wrow = (samp >= 0) ? (g_W + (size_t)samp * N_EMB) : g_W;

    int lane = tid & 31, warp = tid >> 5;
    int g = lane >> 2, t = lane & 3;
    int wm = (warp & 1) * 32;        // m offset of m32 slab
    int wn = (warp >> 1) * 32;       // n offset of n32 slab

    float acc[2][4][4];              // [m16-half][n8-block][frag]
#pragma unroll
    for (int h = 0; h < 2; h++)
#pragma unroll
        for (int j = 0; j < 4; j++)
#pragma unroll
            for (int i = 0; i < 4; i++) acc[h][j][i] = 0.f;

    for (int ch = 0; ch < KCH; ch += KB) {
        // ---- A tile ----
        if (samp >= 0) {
            float4 v0 = *(const float4*)(wrow + kbase + ch + ak8 + 0);
            float4 v1 = *(const float4*)(wrow + kbase + ch + ak8 + 4);
            As[ak8 + 0][am] = __uint_as_float(f2tf(v0.x));
            As[ak8 + 1][am] = __uint_as_float(f2tf(v0.y));
            As[ak8 + 2][am] = __uint_as_float(f2tf(v0.z));
            As[ak8 + 3][am] = __uint_as_float(f2tf(v0.w));
            As[ak8 + 4][am] = __uint_as_float(f2tf(v1.x));
            As[ak8 + 5][am] = __uint_as_float(f2tf(v1.y));
            As[ak8 + 6][am] = __uint_as_float(f2tf(v1.z));
            As[ak8 + 7][am] = __uint_as_float(f2tf(v1.w));
        } else {
#pragma unroll
            for (int j = 0; j < 8; j++) As[ak8 + j][am] = 0.f;
        }
        // ---- B tile ----
        const float* Eb = E + ((size_t)c * N_EMB + kbase + ch) * DIM + d0;
#pragma unroll
        for (int j = 0; j < 4; j++) {
            int f  = j * 256 + tid;
            int r  = f >> 5;
            int c4 = (f & 31) * 4;
            float4 v = *(const float4*)(Eb + (size_t)r * DIM + c4);
            float4 o;
            o.x = __uint_as_float(f2tf(v.x));
            o.y = __uint_as_float(f2tf(v.y));
            o.z = __uint_as_float(f2tf(v.z));
            o.w = __uint_as_float(f2tf(v.w));
            *(float4*)&Bs[r][c4] = o;
        }
        __syncthreads();

        // ---- compute: 4 k8-steps, 16 LDS + 8 HMMA each ----
#pragma unroll
        for (int kk = 0; kk < 4; kk++) {
            int k0 = kk * 8;
            uint32_t a[2][4];
#pragma unroll
            for (int h = 0; h < 2; h++) {
                int mrow = wm + h * 16 + g;
                a[h][0] = __float_as_uint(As[k0 + t][mrow]);
                a[h][1] = __float_as_uint(As[k0 + t][mrow + 8]);
                a[h][2] = __float_as_uint(As[k0 + t + 4][mrow]);
                a[h][3] = __float_as_uint(As[k0 + t + 4][mrow + 8]);
            }
            uint32_t b[4][2];
#pragma unroll
            for (int j = 0; j < 4; j++) {
                int n = wn + j * 8 + g;
                b[j][0] = __float_as_uint(Bs[k0 + t][n]);
                b[j][1] = __float_as_uint(Bs[k0 + t + 4][n]);
            }
#pragma unroll
            for (int h = 0; h < 2; h++)
#pragma unroll
                for (int j = 0; j < 4; j++)
                    HMMA(acc[h][j], a[h][0], a[h][1], a[h][2], a[h][3],
                         b[j][0], b[j][1]);
        }
        __syncthreads();
    }

    // ---- epilogue -> split-K partials ----
    float* pbase = g_part + (size_t)ks * BATCH * DIM;
#pragma unroll
    for (int h = 0; h < 2; h++) {
        int mi1 = wm + h * 16 + g;
        int mi2 = mi1 + 8;
        int b1 = (m0 + mi1 < cnt) ? sord[mi1] : -1;
        int b2 = (m0 + mi2 < cnt) ? sord[mi2] : -1;
#pragma unroll
        for (int j = 0; j < 4; j++) {
            int dcol = d0 + wn + j * 8 + 2 * t;
            if (b1 >= 0)
                *(float2*)(pbase + (size_t)b1 * DIM + dcol) =
                    make_float2(acc[h][j][0], acc[h][j][1]);
            if (b2 >= 0)
                *(float2*)(pbase + (size_t)b2 * DIM + dcol) =
                    make_float2(acc[h][j][2], acc[h][j][3]);
        }
    }
}

// ---------------- kernel 3: fixed-order split-K reduce (MLP 16) ----------
__global__ void __launch_bounds__(256) reduce_kernel(float* __restrict__ out)
{
    const size_t S = (size_t)BATCH * DIM;
    int q = blockIdx.x * 256 + threadIdx.x;     // float4 index, 0..32767
#pragma unroll
    for (int j = 0; j < 4; j++) {
        size_t i = ((size_t)q + (size_t)j * 32768) * 4;
        float4 a = *(const float4*)(g_part + i);
        float4 b = *(const float4*)(g_part + S + i);
        float4 c = *(const float4*)(g_part + 2 * S + i);
        float4 d = *(const float4*)(g_part + 3 * S + i);
        *(float4*)(out + i) = make_float4(
            (a.x + b.x) + (c.x + d.x),
            (a.y + b.y) + (c.y + d.y),
            (a.z + b.z) + (c.z + d.z),
            (a.w + b.w) + (c.w + d.w));
    }
}

// ---------------- launch ----------------
extern "C" void kernel_launch(void* const* d_in, const int* in_sizes, int n_in,
                              void* d_out, int out_size)
{
    const int*   chrom    = (const int*)d_in[0];
    const float* position = (const float*)d_in[1];
    const float* embed    = (const float*)d_in[2];
    const float* centers  = (const float*)d_in[3];
    const float* logv     = (const float*)d_in[4];
    float*       out      = (float*)d_out;

    weights_group_kernel<<<BATCH / 4 + 1, 256>>>(chrom, position, centers, logv);

    dim3 grid(NTILES, KSPLIT * MTILES, NUM_CHR);   // (4, 8, 24)
    gemm_kernel<<<grid, 256>>>(embed);

    reduce_kernel<<<BATCH * DIM / (256 * 16), 256>>>(out);
}